// round 2
// baseline (speedup 1.0000x reference)
#include <cuda_runtime.h>

// Segmented mean-pool: out[b, :] = mean over rows of `samples` owned by bag b.
// samples: [T, 512] fp32 (256 MB)  -> streaming HBM-bound.
// counts:  [B] int64 (or int32 if harness ran JAX without x64 - auto-detected).
// out:     [B, 512] fp32.

#define D_DIM 512
#define COLS4 (D_DIM / 4)          // 128 float4 columns
#define THREADS 128                // one float4 column per thread
#define ROWS_PER_BLOCK 64
#define MAX_BAGS 1024

__device__ long long g_prefix[MAX_BAGS + 1];
__device__ float     g_inv[MAX_BAGS];

// ---------------------------------------------------------------------------
// init: zero the output, build prefix sums + 1/count. Detects counts dtype.
// Block 0 additionally does the scan (n_bags <= blockDim.x assumed for scan
// correctness; B=64 here).
// ---------------------------------------------------------------------------
__global__ void init_kernel(const void* __restrict__ counts_raw,
                            float* __restrict__ out,
                            int n_bags, int out_n, long long total_rows) {
    for (int gid = blockIdx.x * blockDim.x + threadIdx.x; gid < out_n;
         gid += gridDim.x * blockDim.x)
        out[gid] = 0.0f;

    if (blockIdx.x != 0) return;

    __shared__ long long s[MAX_BAGS];
    __shared__ int s_use32;
    int t = threadIdx.x;

    // --- attempt 1: interpret counts as int64 ---
    if (t < n_bags) s[t] = ((const long long*)counts_raw)[t];
    __syncthreads();
    for (int off = 1; off < n_bags; off <<= 1) {
        long long v = (t >= off && t < n_bags) ? s[t - off] : 0;
        __syncthreads();
        if (t < n_bags) s[t] += v;
        __syncthreads();
    }
    if (t == 0) s_use32 = (s[n_bags - 1] != total_rows) ? 1 : 0;
    __syncthreads();

    if (s_use32) {
        // --- attempt 2: interpret counts as int32 ---
        if (t < n_bags) s[t] = (long long)((const int*)counts_raw)[t];
        __syncthreads();
        for (int off = 1; off < n_bags; off <<= 1) {
            long long v = (t >= off && t < n_bags) ? s[t - off] : 0;
            __syncthreads();
            if (t < n_bags) s[t] += v;
            __syncthreads();
        }
    }

    if (t < n_bags) {
        g_prefix[t + 1] = s[t];
        long long lo = (t == 0) ? 0 : s[t - 1];
        long long cnt = s[t] - lo;
        g_inv[t] = (cnt > 0) ? (float)(1.0 / (double)cnt) : 0.0f;
    }
    if (t == 0) g_prefix[0] = 0;
}

// ---------------------------------------------------------------------------
// main pool: each CTA streams ROWS_PER_BLOCK contiguous rows; thread t owns
// float4 column t (perfectly coalesced 2048B/row/CTA). Segment-wise inner
// loop, two independent accumulator chains for MLP, partial sums pre-scaled
// by 1/count and flushed via atomicAdd (~4MB of REDG total - negligible).
// ---------------------------------------------------------------------------
__global__ void __launch_bounds__(THREADS)
pool_kernel(const float4* __restrict__ samples, float* __restrict__ out,
            int n_bags, long long total_rows) {
    __shared__ long long s_pref[MAX_BAGS + 1];
    int t = threadIdx.x;
    for (int i = t; i <= n_bags; i += THREADS) s_pref[i] = g_prefix[i];
    __syncthreads();

    long long row0 = (long long)blockIdx.x * ROWS_PER_BLOCK;
    long long row1 = row0 + ROWS_PER_BLOCK;
    if (row1 > total_rows) row1 = total_rows;
    if (row0 >= row1) return;

    // binary search: largest bag with s_pref[bag] <= row0
    int lo = 0, hi = n_bags;
    while (hi - lo > 1) {
        int mid = (lo + hi) >> 1;
        if (s_pref[mid] <= row0) lo = mid; else hi = mid;
    }
    int bag = lo;

    const int col = t;  // float4 column index
    long long r = row0;
    while (r < row1) {
        long long bag_end = s_pref[bag + 1];
        long long seg_end = (bag_end < row1) ? bag_end : row1;
        float inv = g_inv[bag];

        // two independent accumulator chains (rows interleaved 2-apart)
        float4 acc0 = make_float4(0.f, 0.f, 0.f, 0.f);
        float4 acc1 = make_float4(0.f, 0.f, 0.f, 0.f);
        const float4* p = samples + (size_t)r * COLS4 + col;
        long long n = seg_end - r;
        long long i = 0;
        for (; i + 1 < n; i += 2) {
            float4 a = __ldcs(p);
            float4 b = __ldcs(p + COLS4);
            p += 2 * COLS4;
            acc0.x += a.x; acc0.y += a.y; acc0.z += a.z; acc0.w += a.w;
            acc1.x += b.x; acc1.y += b.y; acc1.z += b.z; acc1.w += b.w;
        }
        if (i < n) {
            float4 a = __ldcs(p);
            acc0.x += a.x; acc0.y += a.y; acc0.z += a.z; acc0.w += a.w;
        }
        r = seg_end;

        float* o = out + (size_t)bag * D_DIM + col * 4;
        atomicAdd(o + 0, (acc0.x + acc1.x) * inv);
        atomicAdd(o + 1, (acc0.y + acc1.y) * inv);
        atomicAdd(o + 2, (acc0.z + acc1.z) * inv);
        atomicAdd(o + 3, (acc0.w + acc1.w) * inv);

        // advance to the bag containing row r (skip any zero-size bags)
        if (r < row1) {
            ++bag;
            while (s_pref[bag + 1] <= r) ++bag;
        }
    }
}

extern "C" void kernel_launch(void* const* d_in, const int* in_sizes, int n_in,
                              void* d_out, int out_size) {
    const float* samples = (const float*)d_in[0];
    const void*  counts  = d_in[1];
    float*       out     = (float*)d_out;

    int n_bags = in_sizes[1];
    if (n_bags > MAX_BAGS) n_bags = MAX_BAGS;
    long long total_rows = (long long)in_sizes[0] / D_DIM;

    int init_blocks = (out_size + 511) / 512;
    if (init_blocks < 1) init_blocks = 1;
    if (init_blocks > 1024) init_blocks = 1024;
    init_kernel<<<init_blocks, 512>>>(counts, out, n_bags, out_size, total_rows);

    int nblocks = (int)((total_rows + ROWS_PER_BLOCK - 1) / ROWS_PER_BLOCK);
    pool_kernel<<<nblocks, THREADS>>>((const float4*)samples, out,
                                      n_bags, total_rows);
}